// round 1
// baseline (speedup 1.0000x reference)
#include <cuda_runtime.h>
#include <math.h>

#define Bz 4
#define Tz 1024
#define Cz 768
#define Hz 12
#define HDz 64
#define Lz 6
#define Vz 32000
#define BT (Bz*Tz)

// ---------------- scratch (static device globals; no allocations) ----------
__device__ float g_x[BT*Cz];        // residual stream
__device__ float g_ln[BT*Cz];       // layernorm output
__device__ float g_qkv[BT*3*Cz];    // qkv projection
__device__ float g_y[BT*Cz];        // attention output (pre-proj)
__device__ float g_h[BT*4*Cz];      // MLP hidden

// ---------------- embedding ------------------------------------------------
__global__ void k_embed(const int* __restrict__ idx,
                        const float* __restrict__ wte,
                        const float* __restrict__ wpe) {
    int i = blockIdx.x * blockDim.x + threadIdx.x;   // over BT*C
    if (i >= BT*Cz) return;
    int c  = i % Cz;
    int bt = i / Cz;
    int t  = bt % Tz;
    int tok = idx[bt];
    g_x[i] = wte[(size_t)tok * Cz + c] + wpe[(size_t)t * Cz + c];
}

// ---------------- layernorm (one block per row, 256 threads, C=768) --------
__global__ void k_ln(const float* __restrict__ x,
                     const float* __restrict__ w,
                     const float* __restrict__ b,
                     float* __restrict__ out) {
    int row = blockIdx.x;
    int tid = threadIdx.x;
    const float* xr = x + (size_t)row * Cz;
    float v0 = xr[tid], v1 = xr[tid + 256], v2 = xr[tid + 512];

    __shared__ float red[256];
    red[tid] = v0 + v1 + v2;
    __syncthreads();
    #pragma unroll
    for (int off = 128; off > 0; off >>= 1) {
        if (tid < off) red[tid] += red[tid + off];
        __syncthreads();
    }
    float mean = red[0] * (1.0f / Cz);
    __syncthreads();

    float d0 = v0 - mean, d1 = v1 - mean, d2 = v2 - mean;
    red[tid] = d0*d0 + d1*d1 + d2*d2;
    __syncthreads();
    #pragma unroll
    for (int off = 128; off > 0; off >>= 1) {
        if (tid < off) red[tid] += red[tid + off];
        __syncthreads();
    }
    float rstd = rsqrtf(red[0] * (1.0f / Cz) + 1e-5f);

    float* orow = out + (size_t)row * Cz;
    orow[tid]       = d0 * rstd * w[tid]       + b[tid];
    orow[tid + 256] = d1 * rstd * w[tid + 256] + b[tid + 256];
    orow[tid + 512] = d2 * rstd * w[tid + 512] + b[tid + 512];
}

// ---------------- tiled fp32 GEMM with fused epilogues ---------------------
// out[M,N] = A[M,K] @ W[K,N]  (+ bias) (+ res | gelu)
// mode: 0 = +bias, 1 = +bias+res, 2 = gelu(+bias), 3 = plain (no bias)
#define GBM 64
#define GBN 64
#define GBK 16
#define GTM 4
#define GTN 4

__device__ __forceinline__ float gelu_exact(float v) {
    return 0.5f * v * (1.0f + erff(v * 0.70710678118654752f));
}

__global__ void k_gemm(const float* __restrict__ A,
                       const float* __restrict__ W,
                       const float* __restrict__ bias,
                       const float* __restrict__ res,
                       float* __restrict__ out,
                       int M, int N, int K, int mode) {
    __shared__ float As[GBK][GBM + 1];
    __shared__ float Bs[GBK][GBN];

    int tid  = threadIdx.x;              // 256 threads
    int tcol = tid % (GBN / GTN);        // 0..15
    int trow = tid / (GBN / GTN);        // 0..15
    int bn0  = blockIdx.x * GBN;
    int bm0  = blockIdx.y * GBM;

    const float* Aptr = A + (size_t)bm0 * K;
    const float* Wptr = W + bn0;

    float acc[GTM][GTN];
    #pragma unroll
    for (int i = 0; i < GTM; i++)
        #pragma unroll
        for (int j = 0; j < GTN; j++) acc[i][j] = 0.f;

    for (int k0 = 0; k0 < K; k0 += GBK) {
        // load A tile (BM x BK) -> As[kk][m]
        #pragma unroll
        for (int i = tid; i < GBM * GBK; i += 256) {
            int m  = i / GBK;
            int kk = i % GBK;
            As[kk][m] = Aptr[(size_t)m * K + k0 + kk];
        }
        // load W tile (BK x BN) -> Bs[kk][n]
        #pragma unroll
        for (int i = tid; i < GBK * GBN; i += 256) {
            int kk = i / GBN;
            int n  = i % GBN;
            Bs[kk][n] = Wptr[(size_t)(k0 + kk) * N + n];
        }
        __syncthreads();

        #pragma unroll
        for (int kk = 0; kk < GBK; kk++) {
            float a[GTM], bb[GTN];
            #pragma unroll
            for (int i = 0; i < GTM; i++) a[i]  = As[kk][trow * GTM + i];
            #pragma unroll
            for (int j = 0; j < GTN; j++) bb[j] = Bs[kk][tcol * GTN + j];
            #pragma unroll
            for (int i = 0; i < GTM; i++)
                #pragma unroll
                for (int j = 0; j < GTN; j++)
                    acc[i][j] += a[i] * bb[j];
        }
        __syncthreads();
    }

    #pragma unroll
    for (int i = 0; i < GTM; i++) {
        int m = bm0 + trow * GTM + i;
        #pragma unroll
        for (int j = 0; j < GTN; j++) {
            int n = bn0 + tcol * GTN + j;
            float v = acc[i][j];
            if (mode != 3) v += bias[n];
            if (mode == 1) v += res[(size_t)m * N + n];
            else if (mode == 2) v = gelu_exact(v);
            out[(size_t)m * N + n] = v;
        }
    }
}

// ---------------- causal attention: one block per (b,h,q) ------------------
__global__ void k_attn(const float* __restrict__ qkv, float* __restrict__ y) {
    int q = blockIdx.x, h = blockIdx.y, b = blockIdx.z;
    int tid = threadIdx.x;                 // 128 threads

    __shared__ float qs[HDz];
    __shared__ float sc[Tz];
    __shared__ float red[128];

    const float* qrow = qkv + ((size_t)(b * Tz + q) * 3 * Cz) + h * HDz;
    if (tid < HDz) qs[tid] = qrow[tid];
    __syncthreads();

    int nk = q + 1;
    float lmax = -1e30f;
    const float4* q4 = (const float4*)qs;
    for (int k = tid; k < nk; k += 128) {
        const float4* k4 =
            (const float4*)(qkv + ((size_t)(b * Tz + k) * 3 * Cz) + Cz + h * HDz);
        float s = 0.f;
        #pragma unroll
        for (int d = 0; d < HDz / 4; d++) {
            float4 kv = k4[d];
            float4 qv = q4[d];
            s += qv.x * kv.x + qv.y * kv.y + qv.z * kv.z + qv.w * kv.w;
        }
        s *= 0.125f;                       // 1/sqrt(64)
        sc[k] = s;
        lmax = fmaxf(lmax, s);
    }
    red[tid] = lmax;
    __syncthreads();
    #pragma unroll
    for (int off = 64; off > 0; off >>= 1) {
        if (tid < off) red[tid] = fmaxf(red[tid], red[tid + off]);
        __syncthreads();
    }
    float m = red[0];
    __syncthreads();

    float lsum = 0.f;
    for (int k = tid; k < nk; k += 128) {
        float p = __expf(sc[k] - m);
        sc[k] = p;
        lsum += p;
    }
    red[tid] = lsum;
    __syncthreads();
    #pragma unroll
    for (int off = 64; off > 0; off >>= 1) {
        if (tid < off) red[tid] += red[tid + off];
        __syncthreads();
    }
    float inv = 1.0f / red[0];
    __syncthreads();

    // P @ V : 64 dims, two key-halves per dim
    int d    = tid & 63;
    int half = tid >> 6;
    float acc = 0.f;
    for (int k = half; k < nk; k += 2) {
        acc += sc[k] * qkv[((size_t)(b * Tz + k) * 3 * Cz) + 2 * Cz + h * HDz + d];
    }
    red[tid] = acc;
    __syncthreads();
    if (tid < 64)
        y[((size_t)(b * Tz + q) * Cz) + h * HDz + tid] =
            (red[tid] + red[tid + 64]) * inv;
}

// ---------------- driver ----------------------------------------------------
extern "C" void kernel_launch(void* const* d_in, const int* in_sizes, int n_in,
                              void* d_out, int out_size) {
    const int*   idx    = (const int*)  d_in[0];
    const float* wte    = (const float*)d_in[1];
    const float* wpe    = (const float*)d_in[2];
    const float* ln1_w  = (const float*)d_in[3];
    const float* ln1_b  = (const float*)d_in[4];
    const float* attn_w = (const float*)d_in[5];
    const float* attn_b = (const float*)d_in[6];
    const float* proj_w = (const float*)d_in[7];
    const float* proj_b = (const float*)d_in[8];
    const float* ln2_w  = (const float*)d_in[9];
    const float* ln2_b  = (const float*)d_in[10];
    const float* fc_w   = (const float*)d_in[11];
    const float* fc_b   = (const float*)d_in[12];
    const float* mlp_w  = (const float*)d_in[13];
    const float* mlp_b  = (const float*)d_in[14];
    const float* lnf_w  = (const float*)d_in[15];
    const float* lnf_b  = (const float*)d_in[16];
    const float* head_w = (const float*)d_in[17];
    float* out = (float*)d_out;

    float *px, *pln, *pqkv, *py, *ph;
    cudaGetSymbolAddress((void**)&px,   g_x);
    cudaGetSymbolAddress((void**)&pln,  g_ln);
    cudaGetSymbolAddress((void**)&pqkv, g_qkv);
    cudaGetSymbolAddress((void**)&py,   g_y);
    cudaGetSymbolAddress((void**)&ph,   g_h);

    // embedding
    {
        int total = BT * Cz;
        k_embed<<<(total + 255) / 256, 256>>>(idx, wte, wpe);
    }

    for (int l = 0; l < Lz; l++) {
        const float* aw = attn_w + (size_t)l * Cz * 3 * Cz;
        const float* ab = attn_b + (size_t)l * 3 * Cz;
        const float* pw = proj_w + (size_t)l * Cz * Cz;
        const float* pb = proj_b + (size_t)l * Cz;
        const float* fw = fc_w   + (size_t)l * Cz * 4 * Cz;
        const float* fb = fc_b   + (size_t)l * 4 * Cz;
        const float* mw = mlp_w  + (size_t)l * 4 * Cz * Cz;
        const float* mb = mlp_b  + (size_t)l * Cz;

        // ln1
        k_ln<<<BT, 256>>>(px, ln1_w + (size_t)l * Cz, ln1_b + (size_t)l * Cz, pln);
        // qkv = ln1(x) @ attn_w + attn_b      [4096, 2304]
        k_gemm<<<dim3(3 * Cz / GBN, BT / GBM), 256>>>(pln, aw, ab, nullptr, pqkv,
                                                      BT, 3 * Cz, Cz, 0);
        // attention
        k_attn<<<dim3(Tz, Hz, Bz), 128>>>(pqkv, py);
        // x = x + y @ proj_w + proj_b         [4096, 768]
        k_gemm<<<dim3(Cz / GBN, BT / GBM), 256>>>(py, pw, pb, px, px,
                                                  BT, Cz, Cz, 1);
        // ln2
        k_ln<<<BT, 256>>>(px, ln2_w + (size_t)l * Cz, ln2_b + (size_t)l * Cz, pln);
        // h = gelu(ln2(x) @ fc_w + fc_b)      [4096, 3072]
        k_gemm<<<dim3(4 * Cz / GBN, BT / GBM), 256>>>(pln, fw, fb, nullptr, ph,
                                                      BT, 4 * Cz, Cz, 2);
        // x = x + h @ mlp_w + mlp_b           [4096, 768]
        k_gemm<<<dim3(Cz / GBN, BT / GBM), 256>>>(ph, mw, mb, px, px,
                                                  BT, Cz, 4 * Cz, 1);
    }

    // final layernorm + head
    k_ln<<<BT, 256>>>(px, lnf_w, lnf_b, pln);
    // logits = lnf(x) @ head_w               [4096, 32000]
    k_gemm<<<dim3(Vz / GBN, BT / GBM), 256>>>(pln, head_w, nullptr, nullptr, out,
                                              BT, Vz, Cz, 3);
}

// round 3
// speedup vs baseline: 1.8541x; 1.8541x over previous
#include <cuda_runtime.h>
#include <cuda_bf16.h>
#include <math.h>
#include <stdint.h>

#define Bz 4
#define Tz 1024
#define Cz 768
#define Hz 12
#define HDz 64
#define Lz 6
#define Vz 32000
#define BT (Bz*Tz)

// ---------------- scratch (static device globals; no allocations) ----------
__device__ float g_x[BT*Cz];                     // residual stream (fp32)
__device__ __nv_bfloat16 g_lnh[BT*Cz], g_lnl[BT*Cz];     // layernorm out hi/lo
__device__ float g_qkv[BT*3*Cz];                 // qkv (fp32, attention input)
__device__ __nv_bfloat16 g_yh[BT*Cz], g_yl[BT*Cz];       // attention out hi/lo
__device__ __nv_bfloat16 g_hh[BT*4*Cz], g_hl[BT*4*Cz];   // MLP hidden hi/lo
// transposed bf16 hi/lo weights: Wt[N,K] row-major (K contiguous)
__device__ __nv_bfloat16 g_wqkv_h[Lz*3*Cz*Cz], g_wqkv_l[Lz*3*Cz*Cz];
__device__ __nv_bfloat16 g_wproj_h[Lz*Cz*Cz],  g_wproj_l[Lz*Cz*Cz];
__device__ __nv_bfloat16 g_wfc_h[Lz*4*Cz*Cz],  g_wfc_l[Lz*4*Cz*Cz];
__device__ __nv_bfloat16 g_wmlp_h[Lz*Cz*4*Cz], g_wmlp_l[Lz*Cz*4*Cz];
__device__ __nv_bfloat16 g_whead_h[Vz*Cz],     g_whead_l[Vz*Cz];

// ---------------- helpers ---------------------------------------------------
__device__ __forceinline__ uint32_t smem_u32(const void* p) {
    uint32_t a;
    asm("{ .reg .u64 t; cvta.to.shared.u64 t, %1; cvt.u32.u64 %0, t; }"
        : "=r"(a) : "l"(p));
    return a;
}
__device__ __forceinline__ void cpasync16(uint32_t s, const void* g) {
    asm volatile("cp.async.cg.shared.global [%0], [%1], 16;\n" :: "r"(s), "l"(g));
}
#define CP_COMMIT() asm volatile("cp.async.commit_group;\n" ::: "memory")

__device__ __forceinline__ void ldm_x4(uint32_t* r, uint32_t addr) {
    asm volatile("ldmatrix.sync.aligned.m8n8.x4.shared.b16 {%0,%1,%2,%3}, [%4];"
        : "=r"(r[0]), "=r"(r[1]), "=r"(r[2]), "=r"(r[3]) : "r"(addr));
}
__device__ __forceinline__ void mma16816(float* d, const uint32_t* a,
                                         uint32_t b0, uint32_t b1) {
    asm volatile("mma.sync.aligned.m16n8k16.row.col.f32.bf16.bf16.f32 "
        "{%0,%1,%2,%3}, {%4,%5,%6,%7}, {%8,%9}, {%0,%1,%2,%3};"
        : "+f"(d[0]), "+f"(d[1]), "+f"(d[2]), "+f"(d[3])
        : "r"(a[0]), "r"(a[1]), "r"(a[2]), "r"(a[3]), "r"(b0), "r"(b1));
}

__device__ __forceinline__ void split_bf16(float v, __nv_bfloat16& hi, __nv_bfloat16& lo) {
    hi = __float2bfloat16(v);
    lo = __float2bfloat16(v - __bfloat162float(hi));
}
__device__ __forceinline__ float gelu_exact(float v) {
    return 0.5f * v * (1.0f + erff(v * 0.70710678118654752f));
}

// ---------------- embedding ------------------------------------------------
__global__ void k_embed(const int* __restrict__ idx,
                        const float* __restrict__ wte,
                        const float* __restrict__ wpe) {
    int i = blockIdx.x * blockDim.x + threadIdx.x;
    if (i >= BT*Cz) return;
    int c  = i % Cz;
    int bt = i / Cz;
    int t  = bt % Tz;
    int tok = idx[bt];
    g_x[i] = wte[(size_t)tok * Cz + c] + wpe[(size_t)t * Cz + c];
}

// ---------------- weight transpose + bf16 hi/lo split ----------------------
__global__ void k_wprep(const float* __restrict__ W,
                        __nv_bfloat16* __restrict__ Whi,
                        __nv_bfloat16* __restrict__ Wlo, int K, int N) {
    __shared__ float t[32][33];
    int n0 = blockIdx.x * 32, k0 = blockIdx.y * 32;
    int tx = threadIdx.x, ty = threadIdx.y;   // 32 x 8
    #pragma unroll
    for (int j = 0; j < 32; j += 8)
        t[ty + j][tx] = W[(size_t)(k0 + ty + j) * N + n0 + tx];
    __syncthreads();
    #pragma unroll
    for (int j = 0; j < 32; j += 8) {
        float v = t[tx][ty + j];
        __nv_bfloat16 hi, lo; split_bf16(v, hi, lo);
        size_t o = (size_t)(n0 + ty + j) * K + k0 + tx;
        Whi[o] = hi; Wlo[o] = lo;
    }
}

// ---------------- layernorm -> bf16 hi/lo ----------------------------------
__global__ void k_ln(const float* __restrict__ x,
                     const float* __restrict__ w,
                     const float* __restrict__ b,
                     __nv_bfloat16* __restrict__ ohi,
                     __nv_bfloat16* __restrict__ olo) {
    int row = blockIdx.x;
    int tid = threadIdx.x;
    const float* xr = x + (size_t)row * Cz;
    float v0 = xr[tid], v1 = xr[tid + 256], v2 = xr[tid + 512];

    __shared__ float red[256];
    red[tid] = v0 + v1 + v2;
    __syncthreads();
    #pragma unroll
    for (int off = 128; off > 0; off >>= 1) {
        if (tid < off) red[tid] += red[tid + off];
        __syncthreads();
    }
    float mean = red[0] * (1.0f / Cz);
    __syncthreads();
    float d0 = v0 - mean, d1 = v1 - mean, d2 = v2 - mean;
    red[tid] = d0*d0 + d1*d1 + d2*d2;
    __syncthreads();
    #pragma unroll
    for (int off = 128; off > 0; off >>= 1) {
        if (tid < off) red[tid] += red[tid + off];
        __syncthreads();
    }
    float rstd = rsqrtf(red[0] * (1.0f / Cz) + 1e-5f);

    size_t base = (size_t)row * Cz;
    float r0 = d0 * rstd * w[tid]       + b[tid];
    float r1 = d1 * rstd * w[tid + 256] + b[tid + 256];
    float r2 = d2 * rstd * w[tid + 512] + b[tid + 512];
    __nv_bfloat16 hi, lo;
    split_bf16(r0, hi, lo); ohi[base + tid]       = hi; olo[base + tid]       = lo;
    split_bf16(r1, hi, lo); ohi[base + tid + 256] = hi; olo[base + tid + 256] = lo;
    split_bf16(r2, hi, lo); ohi[base + tid + 512] = hi; olo[base + tid + 512] = lo;
}

// ---------------- mma.sync GEMM --------------------------------------------
// out[M,N] = (Ahi+Alo)[M,K] @ (Bhi+Blo)[N,K]^T   (3-product bf16 split)
// mode: 0 = +bias->fp32 | 1 = +bias+res->fp32 | 2 = gelu(+bias)->bf16 hi/lo
//       3 = plain->fp32
#define MM_STRIDE_B 80                 // 32 bf16 valid + 8 pad, bytes
#define MM_MAT_BYTES (128*MM_STRIDE_B) // 10240
#define MM_STAGE_BYTES (4*MM_MAT_BYTES)
#define MM_STAGES 3
#define MM_SMEM (MM_STAGES*MM_STAGE_BYTES)

__device__ __forceinline__ void mm_load(
    uint32_t sbase, int stage, int chunk, int tid,
    const __nv_bfloat16* Ahi, const __nv_bfloat16* Alo,
    const __nv_bfloat16* Bhi, const __nv_bfloat16* Blo,
    int gm0, int gn0, int K) {
    int k0 = chunk * 32;
    uint32_t so = sbase + stage * MM_STAGE_BYTES;
    #pragma unroll
    for (int t = 0; t < 8; t++) {
        int idx = tid + t * 256;         // 0..2047
        int mat = idx >> 9;              // 0..3 (const per unrolled iter)
        int rem = idx & 511;
        int row = rem >> 2;
        int seg = rem & 3;
        uint32_t dst = so + mat * MM_MAT_BYTES + row * MM_STRIDE_B + seg * 16;
        size_t off = (mat < 2)
            ? (size_t)(gm0 + row) * K + k0 + seg * 8
            : (size_t)(gn0 + row) * K + k0 + seg * 8;
        const __nv_bfloat16* src =
            (mat == 0 ? Ahi : mat == 1 ? Alo : mat == 2 ? Bhi : Blo) + off;
        cpasync16(dst, src);
    }
    CP_COMMIT();
}

__global__ void __launch_bounds__(256, 1) k_mgemm(
    const __nv_bfloat16* __restrict__ Ahi, const __nv_bfloat16* __restrict__ Alo,
    const __nv_bfloat16* __restrict__ Bhi, const __nv_bfloat16* __restrict__ Blo,
    const float* __restrict__ bias, const float* res,
    float* outf, __nv_bfloat16* outhi, __nv_bfloat16* outlo,
    int M, int N, int K, int mode) {
    extern __shared__ char smem[];
    uint32_t sbase = smem_u32(smem);
    int tid = threadIdx.x, lane = tid & 31, warp = tid >> 5;
    int wm = (warp >> 2) * 64;           // warp M offset (0/64)
    int wn = (warp & 3) * 32;            // warp N offset (0/32/64/96)
    int gn0 = blockIdx.x * 128, gm0 = blockIdx.y * 128;
    int nch = K >> 5;

    float acc[4][4][4];
    #pragma unroll
    for (int i = 0; i < 4; i++)
        #pragma unroll
        for (int j = 0; j < 4; j++)
            #pragma unroll
            for (int e = 0; e < 4; e++) acc[i][j][e] = 0.f;

    mm_load(sbase, 0, 0, tid, Ahi, Alo, Bhi, Blo, gm0, gn0, K);
    mm_load(sbase, 1, 1, tid, Ahi, Alo, Bhi, Blo, gm0, gn0, K);
    mm_load(sbase, 2, 2, tid, Ahi, Alo, Bhi, Blo, gm0, gn0, K);

    int lrow = lane & 15;
    int lk   = (lane >> 4) * 8;          // 0 or 8 (k byte/2 offset within k16)

    for (int i = 0; i < nch; i++) {
        if (i + 2 < nch)      asm volatile("cp.async.wait_group 2;\n" ::: "memory");
        else if (i + 1 < nch) asm volatile("cp.async.wait_group 1;\n" ::: "memory");
        else                  asm volatile("cp.async.wait_group 0;\n" ::: "memory");
        __syncthreads();

        uint32_t so = sbase + (i % 3) * MM_STAGE_BYTES;
        uint32_t arow = so + (wm + lrow) * MM_STRIDE_B;
        uint32_t brow = so + 2 * MM_MAT_BYTES + (wn + lrow) * MM_STRIDE_B;

        #pragma unroll
        for (int ks = 0; ks < 2; ks++) {
            uint32_t kb = (uint32_t)((ks * 16 + lk) * 2);
            uint32_t ah[4][4], al[4][4], bh[2][4], bl[2][4];
            #pragma unroll
            for (int mt = 0; mt < 4; mt++) {
                ldm_x4(ah[mt], arow + mt * (16 * MM_STRIDE_B) + kb);
                ldm_x4(al[mt], arow + MM_MAT_BYTES + mt * (16 * MM_STRIDE_B) + kb);
            }
            #pragma unroll
            for (int np = 0; np < 2; np++) {
                ldm_x4(bh[np], brow + np * (16 * MM_STRIDE_B) + kb);
                ldm_x4(bl[np], brow + MM_MAT_BYTES + np * (16 * MM_STRIDE_B) + kb);
            }
            #pragma unroll
            for (int mt = 0; mt < 4; mt++) {
                #pragma unroll
                for (int nt = 0; nt < 4; nt++) {
                    int np = nt >> 1, h = nt & 1;
                    mma16816(acc[mt][nt], ah[mt], bh[np][h], bh[np][h + 2]);
                    mma16816(acc[mt][nt], al[mt], bh[np][h], bh[np][h + 2]);
                    mma16816(acc[mt][nt], ah[mt], bl[np][h], bl[np][h + 2]);
                }
            }
        }
        __syncthreads();
        if (i + 3 < nch)
            mm_load(sbase, (i + 3) % 3, i + 3, tid, Ahi, Alo, Bhi, Blo, gm0, gn0, K);
    }

    // epilogue
    int r  = lane >> 2;
    int c2 = (lane & 3) * 2;
    #pragma unroll
    for (int mt = 0; mt < 4; mt++) {
        #pragma unroll
        for (int nt = 0; nt < 4; nt++) {
            int m = gm0 + wm + mt * 16 + r;
            int n = gn0 + wn + nt * 8 + c2;
            float* d = acc[mt][nt];
            #pragma unroll
            for (int hh = 0; hh < 2; hh++) {
                int mm = m + hh * 8;
                float v0 = d[2*hh], v1 = d[2*hh + 1];
                if (mode == 2) {
                    v0 = gelu_exact(v0 + bias[n]);
                    v1 = gelu_exact(v1 + bias[n + 1]);
                    __nv_bfloat16 h0, l0, h1, l1;
                    split_bf16(v0, h0, l0); split_bf16(v1, h1, l1);
                    *(__nv_bfloat162*)(outhi + (size_t)mm * N + n) = __nv_bfloat162(h0, h1);
                    *(__nv_bfloat162*)(outlo + (size_t)mm * N + n) = __nv_bfloat162(l0, l1);
                } else {
                    if (mode != 3) { v0 += bias[n]; v1 += bias[n + 1]; }
                    if (mode == 1) {
                        const float2 rv = *(const float2*)(res + (size_t)mm * N + n);
                        v0 += rv.x; v1 += rv.y;
                    }
                    *(float2*)(outf + (size_t)mm * N + n) = make_float2(v0, v1);
                }
            }
        }
    }
}

// ---------------- causal attention: one block per (b,h,q) ------------------
__global__ void k_attn(const float* __restrict__ qkv,
                       __nv_bfloat16* __restrict__ yh,
                       __nv_bfloat16* __restrict__ yl) {
    int q = blockIdx.x, h = blockIdx.y, b = blockIdx.z;
    int tid = threadIdx.x;                 // 128 threads

    __shared__ float qs[HDz];
    __shared__ float sc[Tz];
    __shared__ float red[128];

    const float* qrow = qkv + ((size_t)(b * Tz + q) * 3 * Cz) + h * HDz;
    if (tid < HDz) qs[tid] = qrow[tid];
    __syncthreads();

    int nk = q + 1;
    float lmax = -1e30f;
    const float4* q4 = (const float4*)qs;
    for (int k = tid; k < nk; k += 128) {
        const float4* k4 =
            (const float4*)(qkv + ((size_t)(b * Tz + k) * 3 * Cz) + Cz + h * HDz);
        float s = 0.f;
        #pragma unroll
        for (int d = 0; d < HDz / 4; d++) {
            float4 kv = k4[d];
            float4 qv = q4[d];
            s += qv.x * kv.x + qv.y * kv.y + qv.z * kv.z + qv.w * kv.w;
        }
        s *= 0.125f;
        sc[k] = s;
        lmax = fmaxf(lmax, s);
    }
    red[tid] = lmax;
    __syncthreads();
    #pragma unroll
    for (int off = 64; off > 0; off >>= 1) {
        if (tid < off) red[tid] = fmaxf(red[tid], red[tid + off]);
        __syncthreads();
    }
    float m = red[0];
    __syncthreads();

    float lsum = 0.f;
    for (int k = tid; k < nk; k += 128) {
        float p = __expf(sc[k] - m);
        sc[k] = p;
        lsum += p;
    }
    red[tid] = lsum;
    __syncthreads();
    #pragma unroll
    for (int off = 64; off > 0; off >>= 1) {
        if (tid < off) red[tid] += red[tid + off];
        __syncthreads();
    }
    float inv = 1.0f / red[0];
    __syncthreads();

    int d    = tid & 63;
    int half = tid >> 6;
    float acc = 0.f;
    for (int k = half; k < nk; k += 2) {
        acc += sc[k] * qkv[((size_t)(b * Tz + k) * 3 * Cz) + 2 * Cz + h * HDz + d];
    }
    red[tid] = acc;
    __syncthreads();
    if (tid < 64) {
        float v = (red[tid] + red[tid + 64]) * inv;
        size_t o = ((size_t)(b * Tz + q) * Cz) + h * HDz + tid;
        __nv_bfloat16 hi, lo; split_bf16(v, hi, lo);
        yh[o] = hi; yl[o] = lo;
    }
}

// ---------------- driver ----------------------------------------------------
extern "C" void kernel_launch(void* const* d_in, const int* in_sizes, int n_in,
                              void* d_out, int out_size) {
    const int*   idx    = (const int*)  d_in[0];
    const float* wte    = (const float*)d_in[1];
    const float* wpe    = (const float*)d_in[2];
    const float* ln1_w  = (const float*)d_in[3];
    const float* ln1_b  = (const float*)d_in[4];
    const float* attn_w = (const float*)d_in[5];
    const float* attn_b = (const float*)d_in[6];
    const float* proj_w = (const float*)d_in[7];
    const float* proj_b = (const float*)d_in[8];
    const float* ln2_w  = (const float*)d_in[9];
    const float* ln2_b  = (const float*)d_in[10];
    const float* fc_w   = (const float*)d_in[11];
    const float* fc_b   = (const float*)d_in[12];
    const float* mlp_w  = (const float*)d_in[13];
    const float* mlp_b  = (const float*)d_in[14];
    const float* lnf_w  = (const float*)d_in[15];
    const float* lnf_b  = (const float*)d_in[16];
    const float* head_w = (const float*)d_in[17];
    float* out = (float*)d_out;

    float *px, *pqkv;
    __nv_bfloat16 *plnh, *plnl, *pyh, *pyl, *phh, *phl;
    __nv_bfloat16 *wqh, *wql, *wph, *wpl, *wfh, *wfl, *wmh, *wml, *whh, *whl;
    cudaGetSymbolAddress((void**)&px,   g_x);
    cudaGetSymbolAddress((void**)&pqkv, g_qkv);
    cudaGetSymbolAddress((void**)&plnh, g_lnh);
    cudaGetSymbolAddress((void**)&plnl, g_lnl);
    cudaGetSymbolAddress((void**)&pyh,  g_yh);
    cudaGetSymbolAddress((void**)&pyl,  g_yl);
    cudaGetSymbolAddress((void**)&phh,  g_hh);
    cudaGetSymbolAddress((void**)&phl,  g_hl);
    cudaGetSymbolAddress((void**)&wqh,  g_wqkv_h);
    cudaGetSymbolAddress((void**)&wql,  g_wqkv_l);
    cudaGetSymbolAddress((void**)&wph,  g_wproj_h);
    cudaGetSymbolAddress((void**)&wpl,  g_wproj_l);
    cudaGetSymbolAddress((void**)&wfh,  g_wfc_h);
    cudaGetSymbolAddress((void**)&wfl,  g_wfc_l);
    cudaGetSymbolAddress((void**)&wmh,  g_wmlp_h);
    cudaGetSymbolAddress((void**)&wml,  g_wmlp_l);
    cudaGetSymbolAddress((void**)&whh,  g_whead_h);
    cudaGetSymbolAddress((void**)&whl,  g_whead_l);

    cudaFuncSetAttribute(k_mgemm, cudaFuncAttributeMaxDynamicSharedMemorySize, MM_SMEM);

    dim3 tp(32, 8);
    for (int l = 0; l < Lz; l++) {
        k_wprep<<<dim3(3*Cz/32, Cz/32), tp>>>(attn_w + (size_t)l*Cz*3*Cz,
            wqh + (size_t)l*3*Cz*Cz, wql + (size_t)l*3*Cz*Cz, Cz, 3*Cz);
        k_wprep<<<dim3(Cz/32, Cz/32), tp>>>(proj_w + (size_t)l*Cz*Cz,
            wph + (size_t)l*Cz*Cz, wpl + (size_t)l*Cz*Cz, Cz, Cz);
        k_wprep<<<dim3(4*Cz/32, Cz/32), tp>>>(fc_w + (size_t)l*Cz*4*Cz,
            wfh + (size_t)l*4*Cz*Cz, wfl + (size_t)l*4*Cz*Cz, Cz, 4*Cz);
        k_wprep<<<dim3(Cz/32, 4*Cz/32), tp>>>(mlp_w + (size_t)l*4*Cz*Cz,
            wmh + (size_t)l*Cz*4*Cz, wml + (size_t)l*Cz*4*Cz, 4*Cz, Cz);
    }
    k_wprep<<<dim3(Vz/32, Cz/32), tp>>>(head_w, whh, whl, Cz, Vz);

    k_embed<<<(BT*Cz + 255) / 256, 256>>>(idx, wte, wpe);

    for (int l = 0; l < Lz; l++) {
        const float* ab = attn_b + (size_t)l * 3 * Cz;
        const float* pb = proj_b + (size_t)l * Cz;
        const float* fb = fc_b   + (size_t)l * 4 * Cz;
        const float* mb = mlp_b  + (size_t)l * Cz;

        k_ln<<<BT, 256>>>(px, ln1_w + (size_t)l*Cz, ln1_b + (size_t)l*Cz, plnh, plnl);
        // qkv = ln1 @ Wqkv + b     [4096, 2304]
        k_mgemm<<<dim3(3*Cz/128, BT/128), 256, MM_SMEM>>>(
            plnh, plnl, wqh + (size_t)l*3*Cz*Cz, wql + (size_t)l*3*Cz*Cz,
            ab, nullptr, pqkv, nullptr, nullptr, BT, 3*Cz, Cz, 0);
        k_attn<<<dim3(Tz, Hz, Bz), 128>>>(pqkv, pyh, pyl);
        // x += y @ Wproj + b       [4096, 768]
        k_mgemm<<<dim3(Cz/128, BT/128), 256, MM_SMEM>>>(
            pyh, pyl, wph + (size_t)l*Cz*Cz, wpl + (size_t)l*Cz*Cz,
            pb, px, px, nullptr, nullptr, BT, Cz, Cz, 1);
        k_ln<<<BT, 256>>>(px, ln2_w + (size_t)l*Cz, ln2_b + (size_t)l*Cz, plnh, plnl);
        // h = gelu(ln2 @ Wfc + b)  [4096, 3072] -> bf16 hi/lo
        k_mgemm<<<dim3(4*Cz/128, BT/128), 256, MM_SMEM>>>(
            plnh, plnl, wfh + (size_t)l*4*Cz*Cz, wfl + (size_t)l*4*Cz*Cz,
            fb, nullptr, nullptr, phh, phl, BT, 4*Cz, Cz, 2);
        // x += h @ Wmlp + b        [4096, 768], K=3072
        k_mgemm<<<dim3(Cz/128, BT/128), 256, MM_SMEM>>>(
            phh, phl, wmh + (size_t)l*Cz*4*Cz, wml + (size_t)l*Cz*4*Cz,
            mb, px, px, nullptr, nullptr, BT, Cz, 4*Cz, 1);
    }

    k_ln<<<BT, 256>>>(px, lnf_w, lnf_b, plnh, plnl);
    // logits = lnf @ Whead        [4096, 32000]
    k_mgemm<<<dim3(Vz/128, BT/128), 256, MM_SMEM>>>(
        plnh, plnl, whh, whl, nullptr, nullptr, out, nullptr, nullptr,
        BT, Vz, Cz, 3);
}

// round 4
// speedup vs baseline: 3.1574x; 1.7029x over previous
#include <cuda_runtime.h>
#include <cuda_bf16.h>
#include <math.h>
#include <stdint.h>

#define Bz 4
#define Tz 1024
#define Cz 768
#define Hz 12
#define HDz 64
#define Lz 6
#define Vz 32000
#define BT (Bz*Tz)

// ---------------- scratch (static device globals; no allocations) ----------
__device__ float g_x[BT*Cz];                     // residual stream (fp32)
__device__ __nv_bfloat16 g_lnh[BT*Cz], g_lnl[BT*Cz];     // layernorm out hi/lo
__device__ float g_qkv[BT*3*Cz];                 // qkv (fp32, attention input)
__device__ __nv_bfloat16 g_yh[BT*Cz], g_yl[BT*Cz];       // attention out hi/lo
__device__ __nv_bfloat16 g_hh[BT*4*Cz], g_hl[BT*4*Cz];   // MLP hidden hi/lo
// transposed bf16 hi/lo weights: Wt[N,K] row-major (K contiguous)
__device__ __nv_bfloat16 g_wqkv_h[Lz*3*Cz*Cz], g_wqkv_l[Lz*3*Cz*Cz];
__device__ __nv_bfloat16 g_wproj_h[Lz*Cz*Cz],  g_wproj_l[Lz*Cz*Cz];
__device__ __nv_bfloat16 g_wfc_h[Lz*4*Cz*Cz],  g_wfc_l[Lz*4*Cz*Cz];
__device__ __nv_bfloat16 g_wmlp_h[Lz*Cz*4*Cz], g_wmlp_l[Lz*Cz*4*Cz];
__device__ __nv_bfloat16 g_whead_h[Vz*Cz],     g_whead_l[Vz*Cz];

// ---------------- helpers ---------------------------------------------------
__device__ __forceinline__ uint32_t smem_u32(const void* p) {
    uint32_t a;
    asm("{ .reg .u64 t; cvta.to.shared.u64 t, %1; cvt.u32.u64 %0, t; }"
        : "=r"(a) : "l"(p));
    return a;
}
__device__ __forceinline__ void cpasync16(uint32_t s, const void* g) {
    asm volatile("cp.async.cg.shared.global [%0], [%1], 16;\n" :: "r"(s), "l"(g));
}
#define CP_COMMIT() asm volatile("cp.async.commit_group;\n" ::: "memory")

__device__ __forceinline__ void ldm_x4(uint32_t* r, uint32_t addr) {
    asm volatile("ldmatrix.sync.aligned.m8n8.x4.shared.b16 {%0,%1,%2,%3}, [%4];"
        : "=r"(r[0]), "=r"(r[1]), "=r"(r[2]), "=r"(r[3]) : "r"(addr));
}
__device__ __forceinline__ void mma16816(float* d, const uint32_t* a,
                                         uint32_t b0, uint32_t b1) {
    asm volatile("mma.sync.aligned.m16n8k16.row.col.f32.bf16.bf16.f32 "
        "{%0,%1,%2,%3}, {%4,%5,%6,%7}, {%8,%9}, {%0,%1,%2,%3};"
        : "+f"(d[0]), "+f"(d[1]), "+f"(d[2]), "+f"(d[3])
        : "r"(a[0]), "r"(a[1]), "r"(a[2]), "r"(a[3]), "r"(b0), "r"(b1));
}

__device__ __forceinline__ void split_bf16(float v, __nv_bfloat16& hi, __nv_bfloat16& lo) {
    hi = __float2bfloat16(v);
    lo = __float2bfloat16(v - __bfloat162float(hi));
}
__device__ __forceinline__ float gelu_exact(float v) {
    return 0.5f * v * (1.0f + erff(v * 0.70710678118654752f));
}

// ---------------- embedding ------------------------------------------------
__global__ void k_embed(const int* __restrict__ idx,
                        const float* __restrict__ wte,
                        const float* __restrict__ wpe) {
    int i = blockIdx.x * blockDim.x + threadIdx.x;
    if (i >= BT*Cz) return;
    int c  = i % Cz;
    int bt = i / Cz;
    int t  = bt % Tz;
    int tok = idx[bt];
    g_x[i] = wte[(size_t)tok * Cz + c] + wpe[(size_t)t * Cz + c];
}

// ---------------- weight transpose + bf16 hi/lo split ----------------------
__global__ void k_wprep(const float* __restrict__ W,
                        __nv_bfloat16* __restrict__ Whi,
                        __nv_bfloat16* __restrict__ Wlo, int K, int N) {
    __shared__ float t[32][33];
    int n0 = blockIdx.x * 32, k0 = blockIdx.y * 32;
    int tx = threadIdx.x, ty = threadIdx.y;   // 32 x 8
    #pragma unroll
    for (int j = 0; j < 32; j += 8)
        t[ty + j][tx] = W[(size_t)(k0 + ty + j) * N + n0 + tx];
    __syncthreads();
    #pragma unroll
    for (int j = 0; j < 32; j += 8) {
        float v = t[tx][ty + j];
        __nv_bfloat16 hi, lo; split_bf16(v, hi, lo);
        size_t o = (size_t)(n0 + ty + j) * K + k0 + tx;
        Whi[o] = hi; Wlo[o] = lo;
    }
}

// ---------------- layernorm -> bf16 hi/lo ----------------------------------
__global__ void k_ln(const float* __restrict__ x,
                     const float* __restrict__ w,
                     const float* __restrict__ b,
                     __nv_bfloat16* __restrict__ ohi,
                     __nv_bfloat16* __restrict__ olo) {
    int row = blockIdx.x;
    int tid = threadIdx.x;
    const float* xr = x + (size_t)row * Cz;
    float v0 = xr[tid], v1 = xr[tid + 256], v2 = xr[tid + 512];

    __shared__ float red[256];
    red[tid] = v0 + v1 + v2;
    __syncthreads();
    #pragma unroll
    for (int off = 128; off > 0; off >>= 1) {
        if (tid < off) red[tid] += red[tid + off];
        __syncthreads();
    }
    float mean = red[0] * (1.0f / Cz);
    __syncthreads();
    float d0 = v0 - mean, d1 = v1 - mean, d2 = v2 - mean;
    red[tid] = d0*d0 + d1*d1 + d2*d2;
    __syncthreads();
    #pragma unroll
    for (int off = 128; off > 0; off >>= 1) {
        if (tid < off) red[tid] += red[tid + off];
        __syncthreads();
    }
    float rstd = rsqrtf(red[0] * (1.0f / Cz) + 1e-5f);

    size_t base = (size_t)row * Cz;
    float r0 = d0 * rstd * w[tid]       + b[tid];
    float r1 = d1 * rstd * w[tid + 256] + b[tid + 256];
    float r2 = d2 * rstd * w[tid + 512] + b[tid + 512];
    __nv_bfloat16 hi, lo;
    split_bf16(r0, hi, lo); ohi[base + tid]       = hi; olo[base + tid]       = lo;
    split_bf16(r1, hi, lo); ohi[base + tid + 256] = hi; olo[base + tid + 256] = lo;
    split_bf16(r2, hi, lo); ohi[base + tid + 512] = hi; olo[base + tid + 512] = lo;
}

// ---------------- mma.sync GEMM, K-chunk 64, 2-stage -----------------------
// out[M,N] = (Ahi+Alo)[M,K] @ (Bhi+Blo)[N,K]^T   (3-product bf16 split)
// mode: 0 = +bias->fp32 | 1 = +bias+res->fp32 | 2 = gelu(+bias)->bf16 hi/lo
//       3 = plain->fp32.   BM = 32*MT (64 or 128); BN = 128.
#define MMR 144                        // row stride bytes (128 data + 16 pad)

template<int MT>
__device__ __forceinline__ void mm_load(
    uint32_t so, int chunk, int tid,
    const __nv_bfloat16* Ahi, const __nv_bfloat16* Alo,
    const __nv_bfloat16* Bhi, const __nv_bfloat16* Blo,
    int gm0, int gn0, int K) {
    constexpr int BM = MT * 32;
    constexpr int ABYTES = BM * MMR;
    constexpr int BBYTES = 128 * MMR;
    int k0 = chunk * 64;
    constexpr int TOT = (2 * BM + 256) * 8;
    #pragma unroll
    for (int i = tid; i < TOT; i += 256) {
        int r = i >> 3, seg = i & 7;
        const __nv_bfloat16* src;
        uint32_t dst;
        if (r < BM) {
            src = Ahi + (size_t)(gm0 + r) * K;
            dst = so + r * MMR;
        } else if (r < 2 * BM) {
            int rr = r - BM;
            src = Alo + (size_t)(gm0 + rr) * K;
            dst = so + ABYTES + rr * MMR;
        } else if (r < 2 * BM + 128) {
            int rr = r - 2 * BM;
            src = Bhi + (size_t)(gn0 + rr) * K;
            dst = so + 2 * ABYTES + rr * MMR;
        } else {
            int rr = r - 2 * BM - 128;
            src = Blo + (size_t)(gn0 + rr) * K;
            dst = so + 2 * ABYTES + BBYTES + rr * MMR;
        }
        cpasync16(dst + seg * 16, src + k0 + seg * 8);
    }
    CP_COMMIT();
}

template<int MT>
__global__ void __launch_bounds__(256, 1) k_mgemm(
    const __nv_bfloat16* __restrict__ Ahi, const __nv_bfloat16* __restrict__ Alo,
    const __nv_bfloat16* __restrict__ Bhi, const __nv_bfloat16* __restrict__ Blo,
    const float* __restrict__ bias, const float* res,
    float* outf, __nv_bfloat16* outhi, __nv_bfloat16* outlo,
    int M, int N, int K, int mode) {
    constexpr int BM = MT * 32;
    constexpr int ABYTES = BM * MMR;
    constexpr int BBYTES = 128 * MMR;
    constexpr int STAGE = 2 * ABYTES + 2 * BBYTES;
    extern __shared__ char smem[];
    uint32_t sbase = smem_u32(smem);
    int tid = threadIdx.x, lane = tid & 31, warp = tid >> 5;
    int wm = (warp >> 2) * (MT * 16);    // warp M offset
    int wn = (warp & 3) * 32;            // warp N offset
    int gn0 = blockIdx.x * 128, gm0 = blockIdx.y * BM;
    int nch = K >> 6;

    float acc[MT][4][4];
    #pragma unroll
    for (int i = 0; i < MT; i++)
        #pragma unroll
        for (int j = 0; j < 4; j++)
            #pragma unroll
            for (int e = 0; e < 4; e++) acc[i][j][e] = 0.f;

    mm_load<MT>(sbase,         0, tid, Ahi, Alo, Bhi, Blo, gm0, gn0, K);
    mm_load<MT>(sbase + STAGE, 1, tid, Ahi, Alo, Bhi, Blo, gm0, gn0, K);

    int lrow = lane & 15;
    int lkb  = (lane >> 4) * 16;         // k-half byte offset

    for (int i = 0; i < nch; i++) {
        if (i + 1 < nch) asm volatile("cp.async.wait_group 1;\n" ::: "memory");
        else             asm volatile("cp.async.wait_group 0;\n" ::: "memory");
        __syncthreads();

        uint32_t so = sbase + (i & 1) * STAGE;
        uint32_t arow = so + (wm + lrow) * MMR;
        uint32_t brow = so + 2 * ABYTES + (wn + lrow) * MMR;

        #pragma unroll
        for (int ks = 0; ks < 4; ks++) {
            uint32_t kb = (uint32_t)(ks * 32) + lkb;
            uint32_t ah[MT][4], al[MT][4], bh[2][4], bl[2][4];
            #pragma unroll
            for (int mt = 0; mt < MT; mt++) {
                ldm_x4(ah[mt], arow + mt * (16 * MMR) + kb);
                ldm_x4(al[mt], arow + ABYTES + mt * (16 * MMR) + kb);
            }
            #pragma unroll
            for (int np = 0; np < 2; np++) {
                ldm_x4(bh[np], brow + np * (16 * MMR) + kb);
                ldm_x4(bl[np], brow + BBYTES + np * (16 * MMR) + kb);
            }
            #pragma unroll
            for (int mt = 0; mt < MT; mt++) {
                #pragma unroll
                for (int nt = 0; nt < 4; nt++) {
                    int np = nt >> 1, h = nt & 1;
                    mma16816(acc[mt][nt], ah[mt], bh[np][h], bh[np][h + 2]);
                    mma16816(acc[mt][nt], al[mt], bh[np][h], bh[np][h + 2]);
                    mma16816(acc[mt][nt], ah[mt], bl[np][h], bl[np][h + 2]);
                }
            }
        }
        __syncthreads();
        if (i + 2 < nch)
            mm_load<MT>(sbase + (i & 1) * STAGE, i + 2, tid,
                        Ahi, Alo, Bhi, Blo, gm0, gn0, K);
    }

    // epilogue
    int r  = lane >> 2;
    int c2 = (lane & 3) * 2;
    #pragma unroll
    for (int mt = 0; mt < MT; mt++) {
        #pragma unroll
        for (int nt = 0; nt < 4; nt++) {
            int m = gm0 + wm + mt * 16 + r;
            int n = gn0 + wn + nt * 8 + c2;
            float* d = acc[mt][nt];
            #pragma unroll
            for (int hh = 0; hh < 2; hh++) {
                int mm = m + hh * 8;
                float v0 = d[2*hh], v1 = d[2*hh + 1];
                if (mode == 2) {
                    v0 = gelu_exact(v0 + bias[n]);
                    v1 = gelu_exact(v1 + bias[n + 1]);
                    __nv_bfloat16 h0, l0, h1, l1;
                    split_bf16(v0, h0, l0); split_bf16(v1, h1, l1);
                    *(__nv_bfloat162*)(outhi + (size_t)mm * N + n) = __nv_bfloat162(h0, h1);
                    *(__nv_bfloat162*)(outlo + (size_t)mm * N + n) = __nv_bfloat162(l0, l1);
                } else {
                    if (mode != 3) { v0 += bias[n]; v1 += bias[n + 1]; }
                    if (mode == 1) {
                        const float2 rv = *(const float2*)(res + (size_t)mm * N + n);
                        v0 += rv.x; v1 += rv.y;
                    }
                    *(float2*)(outf + (size_t)mm * N + n) = make_float2(v0, v1);
                }
            }
        }
    }
}

// ---------------- flash-tiled causal attention -----------------------------
// block = (q-tile 64, h, b); 256 threads, 8 warps; warp owns 8 query rows.
// lane = r*4 + c : r = local row (0..7), c = key/dim group (0..3).
// lane handles keys {c, c+4, ..., c+60} and output dims [c*16, c*16+16).
#define ASTR 68                         // floats per smem row (272B, 16B-mult)
#define ASMEM (4 * 64 * ASTR * 4)       // Qs, Ks, Vs, Ps

__global__ void __launch_bounds__(256) k_fattn(
    const float* __restrict__ qkv,
    __nv_bfloat16* __restrict__ yh, __nv_bfloat16* __restrict__ yl) {
    extern __shared__ float sm[];
    float* Qs = sm;
    float* Ks = sm + 64 * ASTR;
    float* Vs = sm + 2 * 64 * ASTR;
    float* Ps = sm + 3 * 64 * ASTR;

    int q0 = blockIdx.x * 64, h = blockIdx.y, b = blockIdx.z;
    int tid = threadIdx.x, lane = tid & 31, warp = tid >> 5;
    int r = lane >> 2, c = lane & 3;
    int qrow = warp * 8 + r;             // local query row
    int qglob = q0 + qrow;

    // load Q tile (64 rows x 16 float4)
    {
        const float4* g = (const float4*)qkv;
        float4* s4 = (float4*)Qs;
        for (int i = tid; i < 1024; i += 256) {
            int row = i >> 4, sg = i & 15;
            s4[row * 17 + sg] = g[((size_t)(b * Tz + q0 + row) * (3*Cz) + h * 64) / 4 + sg];
        }
    }

    float mrow = -1e30f, lrow = 0.f;
    float oacc[16];
    #pragma unroll
    for (int i = 0; i < 16; i++) oacc[i] = 0.f;

    int ntiles = (q0 >> 6) + 1;
    for (int t = 0; t < ntiles; t++) {
        __syncthreads();                 // prev Ks/Vs reads done
        {
            const float4* g = (const float4*)qkv;
            float4* k4 = (float4*)Ks;
            float4* v4 = (float4*)Vs;
            for (int i = tid; i < 1024; i += 256) {
                int row = i >> 4, sg = i & 15;
                size_t gb = ((size_t)(b * Tz + t * 64 + row) * (3*Cz) + h * 64) / 4 + sg;
                k4[row * 17 + sg] = g[gb + Cz / 4];
                v4[row * 17 + sg] = g[gb + 2 * Cz / 4];
            }
        }
        __syncthreads();

        // scores for 16 keys: key = kk*4 + c
        float s[16];
        #pragma unroll
        for (int kk = 0; kk < 16; kk++) s[kk] = 0.f;
        const float4* q4 = (const float4*)Qs + qrow * 17;
        const float4* k4b = (const float4*)Ks;
        #pragma unroll 4
        for (int d4 = 0; d4 < 16; d4++) {
            float4 qv = q4[d4];
            #pragma unroll
            for (int kk = 0; kk < 16; kk++) {
                float4 kv = k4b[(kk * 4 + c) * 17 + d4];
                s[kk] += qv.x * kv.x + qv.y * kv.y + qv.z * kv.z + qv.w * kv.w;
            }
        }
        bool maskt = (t == ntiles - 1);
        float tmax = -1e30f;
        #pragma unroll
        for (int kk = 0; kk < 16; kk++) {
            s[kk] *= 0.125f;
            if (maskt && (t * 64 + kk * 4 + c) > qglob) s[kk] = -1e30f;
            tmax = fmaxf(tmax, s[kk]);
        }
        tmax = fmaxf(tmax, __shfl_xor_sync(0xffffffffu, tmax, 1));
        tmax = fmaxf(tmax, __shfl_xor_sync(0xffffffffu, tmax, 2));
        float mnew = fmaxf(mrow, tmax);
        float scale = __expf(mrow - mnew);
        float psum = 0.f;
        #pragma unroll
        for (int kk = 0; kk < 16; kk++) {
            float p = __expf(s[kk] - mnew);
            s[kk] = p;
            psum += p;
            Ps[qrow * ASTR + kk * 4 + c] = p;
        }
        psum += __shfl_xor_sync(0xffffffffu, psum, 1);
        psum += __shfl_xor_sync(0xffffffffu, psum, 2);
        lrow = lrow * scale + psum;
        #pragma unroll
        for (int i = 0; i < 16; i++) oacc[i] *= scale;
        mrow = mnew;
        __syncwarp();

        // PV: dims c*16..c*16+15
        const float4* p4 = (const float4*)Ps + qrow * 17;
        const float4* v4b = (const float4*)Vs;
        #pragma unroll 2
        for (int kq = 0; kq < 16; kq++) {
            float4 pv = p4[kq];
            #pragma unroll
            for (int j = 0; j < 4; j++) {
                float pj = (j == 0) ? pv.x : (j == 1) ? pv.y : (j == 2) ? pv.z : pv.w;
                const float4* vr = v4b + (kq * 4 + j) * 17 + c * 4;
                #pragma unroll
                for (int e = 0; e < 4; e++) {
                    float4 vv = vr[e];
                    oacc[e*4+0] += pj * vv.x;
                    oacc[e*4+1] += pj * vv.y;
                    oacc[e*4+2] += pj * vv.z;
                    oacc[e*4+3] += pj * vv.w;
                }
            }
        }
    }

    float inv = 1.0f / lrow;
    size_t base = (size_t)(b * Tz + qglob) * Cz + h * 64 + c * 16;
    #pragma unroll
    for (int g = 0; g < 8; g++) {
        float v0 = oacc[2*g] * inv, v1 = oacc[2*g+1] * inv;
        __nv_bfloat16 h0, l0, h1, l1;
        split_bf16(v0, h0, l0); split_bf16(v1, h1, l1);
        *(__nv_bfloat162*)(yh + base + 2*g) = __nv_bfloat162(h0, h1);
        *(__nv_bfloat162*)(yl + base + 2*g) = __nv_bfloat162(l0, l1);
    }
}

// ---------------- driver ----------------------------------------------------
extern "C" void kernel_launch(void* const* d_in, const int* in_sizes, int n_in,
                              void* d_out, int out_size) {
    const int*   idx    = (const int*)  d_in[0];
    const float* wte    = (const float*)d_in[1];
    const float* wpe    = (const float*)d_in[2];
    const float* ln1_w  = (const float*)d_in[3];
    const float* ln1_b  = (const float*)d_in[4];
    const float* attn_w = (const float*)d_in[5];
    const float* attn_b = (const float*)d_in[6];
    const float* proj_w = (const float*)d_in[7];
    const float* proj_b = (const float*)d_in[8];
    const float* ln2_w  = (const float*)d_in[9];
    const float* ln2_b  = (const float*)d_in[10];
    const float* fc_w   = (const float*)d_in[11];
    const float* fc_b   = (const float*)d_in[12];
    const float* mlp_w  = (const float*)d_in[13];
    const float* mlp_b  = (const float*)d_in[14];
    const float* lnf_w  = (const float*)d_in[15];
    const float* lnf_b  = (const float*)d_in[16];
    const float* head_w = (const float*)d_in[17];
    float* out = (float*)d_out;

    float *px, *pqkv;
    __nv_bfloat16 *plnh, *plnl, *pyh, *pyl, *phh, *phl;
    __nv_bfloat16 *wqh, *wql, *wph, *wpl, *wfh, *wfl, *wmh, *wml, *whh, *whl;
    cudaGetSymbolAddress((void**)&px,   g_x);
    cudaGetSymbolAddress((void**)&pqkv, g_qkv);
    cudaGetSymbolAddress((void**)&plnh, g_lnh);
    cudaGetSymbolAddress((void**)&plnl, g_lnl);
    cudaGetSymbolAddress((void**)&pyh,  g_yh);
    cudaGetSymbolAddress((void**)&pyl,  g_yl);
    cudaGetSymbolAddress((void**)&phh,  g_hh);
    cudaGetSymbolAddress((void**)&phl,  g_hl);
    cudaGetSymbolAddress((void**)&wqh,  g_wqkv_h);
    cudaGetSymbolAddress((void**)&wql,  g_wqkv_l);
    cudaGetSymbolAddress((void**)&wph,  g_wproj_h);
    cudaGetSymbolAddress((void**)&wpl,  g_wproj_l);
    cudaGetSymbolAddress((void**)&wfh,  g_wfc_h);
    cudaGetSymbolAddress((void**)&wfl,  g_wfc_l);
    cudaGetSymbolAddress((void**)&wmh,  g_wmlp_h);
    cudaGetSymbolAddress((void**)&wml,  g_wmlp_l);
    cudaGetSymbolAddress((void**)&whh,  g_whead_h);
    cudaGetSymbolAddress((void**)&whl,  g_whead_l);

    const int SM4 = 2 * (2 * 128 * MMR + 2 * 128 * MMR);   // 147456
    const int SM2 = 2 * (2 * 64 * MMR + 2 * 128 * MMR);    // 110592
    cudaFuncSetAttribute(k_mgemm<4>, cudaFuncAttributeMaxDynamicSharedMemorySize, SM4);
    cudaFuncSetAttribute(k_mgemm<2>, cudaFuncAttributeMaxDynamicSharedMemorySize, SM2);
    cudaFuncSetAttribute(k_fattn,    cudaFuncAttributeMaxDynamicSharedMemorySize, ASMEM);

    dim3 tp(32, 8);
    // ---- launches 1-5: layer-0 weight preps + embed + ln1 (so launch #6,
    // the ncu-captured one, is the big QKV k_mgemm) ----
    k_wprep<<<dim3(3*Cz/32, Cz/32), tp>>>(attn_w, wqh, wql, Cz, 3*Cz);      // 1
    k_wprep<<<dim3(Cz/32, Cz/32), tp>>>(proj_w, wph, wpl, Cz, Cz);          // 2
    k_embed<<<(BT*Cz + 255) / 256, 256>>>(idx, wte, wpe);                   // 3
    k_ln<<<BT, 256>>>(px, ln1_w, ln1_b, plnh, plnl);                        // 4
    k_wprep<<<dim3(4*Cz/32, Cz/32), tp>>>(fc_w, wfh, wfl, Cz, 4*Cz);        // 5
    // launch 6: QKV GEMM of layer 0
    k_mgemm<4><<<dim3(3*Cz/128, BT/128), 256, SM4>>>(
        plnh, plnl, wqh, wql, attn_b, nullptr, pqkv, nullptr, nullptr,
        BT, 3*Cz, Cz, 0);

    // remaining weight preps
    k_wprep<<<dim3(Cz/32, 4*Cz/32), tp>>>(mlp_w, wmh, wml, 4*Cz, Cz);
    for (int l = 1; l < Lz; l++) {
        k_wprep<<<dim3(3*Cz/32, Cz/32), tp>>>(attn_w + (size_t)l*Cz*3*Cz,
            wqh + (size_t)l*3*Cz*Cz, wql + (size_t)l*3*Cz*Cz, Cz, 3*Cz);
        k_wprep<<<dim3(Cz/32, Cz/32), tp>>>(proj_w + (size_t)l*Cz*Cz,
            wph + (size_t)l*Cz*Cz, wpl + (size_t)l*Cz*Cz, Cz, Cz);
        k_wprep<<<dim3(4*Cz/32, Cz/32), tp>>>(fc_w + (size_t)l*Cz*4*Cz,
            wfh + (size_t)l*4*Cz*Cz, wfl + (size_t)l*4*Cz*Cz, Cz, 4*Cz);
        k_wprep<<<dim3(Cz/32, 4*Cz/32), tp>>>(mlp_w + (size_t)l*4*Cz*Cz,
            wmh + (size_t)l*Cz*4*Cz, wml + (size_t)l*Cz*4*Cz, 4*Cz, Cz);
    }
    k_wprep<<<dim3(Vz/32, Cz/32), tp>>>(head_w, whh, whl, Cz, Vz);

    for (int l = 0; l < Lz; l++) {
        const float* ab = attn_b + (size_t)l * 3 * Cz;
        const float* pb = proj_b + (size_t)l * Cz;
        const float* fb = fc_b   + (size_t)l * 4 * Cz;
        const float* mb = mlp_b  + (size_t)l * Cz;

        if (l > 0) {
            k_ln<<<BT, 256>>>(px, ln1_w + (size_t)l*Cz, ln1_b + (size_t)l*Cz, plnh, plnl);
            k_mgemm<4><<<dim3(3*Cz/128, BT/128), 256, SM4>>>(
                plnh, plnl, wqh + (size_t)l*3*Cz*Cz, wql + (size_t)l*3*Cz*Cz,
                ab, nullptr, pqkv, nullptr, nullptr, BT, 3*Cz, Cz, 0);
        }
        k_fattn<<<dim3(Tz/64, Hz, Bz), 256, ASMEM>>>(pqkv, pyh, pyl);
        // x += y @ Wproj + b       [4096, 768] (64-row M tiles)
        k_mgemm<2><<<dim3(Cz/128, BT/64), 256, SM2>>>(
            pyh, pyl, wph + (size_t)l*Cz*Cz, wpl + (size_t)l*Cz*Cz,
            pb, px, px, nullptr, nullptr, BT, Cz, Cz, 1);
        k_ln<<<BT, 256>>>(px, ln2_w + (size_t)l*Cz, ln2_b + (size_t)l*Cz, plnh, plnl);
        // h = gelu(ln2 @ Wfc + b)  [4096, 3072]
        k_mgemm<4><<<dim3(4*Cz/128, BT/128), 256, SM4>>>(
            plnh, plnl, wfh + (size_t)l*4*Cz*Cz, wfl + (size_t)l*4*Cz*Cz,
            fb, nullptr, nullptr, phh, phl, BT, 4*Cz, Cz, 2);
        // x += h @ Wmlp + b        [4096, 768], K=3072 (64-row M tiles)
        k_mgemm<2><<<dim3(Cz/128, BT/64), 256, SM2>>>(
            phh, phl, wmh + (size_t)l*Cz*4*Cz, wml + (size_t)l*Cz*4*Cz,
            mb, px, px, nullptr, nullptr, BT, Cz, 4*Cz, 1);
    }

    k_ln<<<BT, 256>>>(px, lnf_w, lnf_b, plnh, plnl);
    // logits = lnf @ Whead        [4096, 32000]
    k_mgemm<4><<<dim3(Vz/128, BT/128), 256, SM4>>>(
        plnh, plnl, whh, whl, nullptr, nullptr, out, nullptr, nullptr,
        BT, Vz, Cz, 3);
}